// round 12
// baseline (speedup 1.0000x reference)
#include <cuda_runtime.h>
#include <cuda_bf16.h>
#include <cstdint>

// ============================================================================
// 2-layer LSTM (H=32, T=7, F=1) + fc(H,1) + fc1(T,1), B=262144.
// R12 = R10 (best: 1284us) + t=0 PEEL: at t=0 both h and c are exactly zero,
// so the layer-0 h-GEMV and layer-1 h-GEMV (512 of 5376 k-iters/thread,
// 9.5% of all work) are skipped bit-identically. Main loop runs t=1..6 with
// unconditional c prefetch. E=2 elems/thread, NT=320 (10 warps/SM),
// broadcast LDS.128 weights + LDS.64 h per k-iter -> 16 FFMA2 (f32x2),
// c-state in gmem scratch, h in SMEM, h-new staged in regs.
// ============================================================================

typedef unsigned long long u64;

#define NT 320          // threads per CTA (10 warps)
#define EPC (2 * NT)    // batch elements per CTA
#define BMAX 524288ull  // scratch capacity (>= B)

__device__ u64 g_cstate[32ull * BMAX];

__device__ __forceinline__ u64 pk2(float lo, float hi) {
    u64 r; asm("mov.b64 %0,{%1,%2};" : "=l"(r) : "f"(lo), "f"(hi)); return r;
}
__device__ __forceinline__ u64 bc2(float v) { return pk2(v, v); }
__device__ __forceinline__ void upk2(u64 v, float& lo, float& hi) {
    asm("mov.b64 {%0,%1},%2;" : "=f"(lo), "=f"(hi) : "l"(v));
}
__device__ __forceinline__ u64 fma2(u64 a, u64 b, u64 c) {
    u64 d; asm("fma.rn.f32x2 %0,%1,%2,%3;" : "=l"(d) : "l"(a), "l"(b), "l"(c)); return d;
}
__device__ __forceinline__ u64 mul2(u64 a, u64 b) {
    u64 d; asm("mul.rn.f32x2 %0,%1,%2;" : "=l"(d) : "l"(a), "l"(b)); return d;
}
__device__ __forceinline__ float ex2f(float x) {
    float y; asm("ex2.approx.f32 %0,%1;" : "=f"(y) : "f"(x)); return y;
}
__device__ __forceinline__ float rcpf(float x) {
    float y; asm("rcp.approx.f32 %0,%1;" : "=f"(y) : "f"(x)); return y;
}
__device__ __forceinline__ float fsig(float x) {
    float e = ex2f(-1.4426950408889634f * x);
    return rcpf(1.0f + e);
}
__device__ __forceinline__ float ftanhx(float x) {
    float t = fminf(-2.8853900817779268f * x, 120.0f);
    float e = ex2f(t);
    float r = rcpf(1.0f + e);
    return fmaf(-e, r, r);
}
__device__ __forceinline__ u64 sig2(u64 z) {
    float a, b; upk2(z, a, b); return pk2(fsig(a), fsig(b));
}
__device__ __forceinline__ u64 tanh2(u64 z) {
    float a, b; upk2(z, a, b); return pk2(ftanhx(a), ftanhx(b));
}

// Full gate update (t>0): c' = f*c + i*g
template <bool DOACC>
__device__ __forceinline__ u64 lstm_upd(
    u64 zi, u64 zf, u64 zg, u64 zo, u64& c, u64 wo, u64& acc)
{
    u64 i2 = sig2(zi);
    u64 f2 = sig2(zf);
    u64 g2 = tanh2(zg);
    u64 o2 = sig2(zo);
    c = fma2(f2, c, mul2(i2, g2));
    u64 h2 = mul2(o2, tanh2(c));
    if (DOACC) acc = fma2(h2, wo, acc);
    return h2;
}

// t=0 gate update: c_prev = 0 exactly -> c' = i*g (f gate multiplies zero).
template <bool DOACC>
__device__ __forceinline__ u64 lstm_upd0(
    u64 zi, u64 zg, u64 zo, u64& c, u64 wo, u64& acc)
{
    u64 i2 = sig2(zi);
    u64 g2 = tanh2(zg);
    u64 o2 = sig2(zo);
    c = mul2(i2, g2);
    u64 h2 = mul2(o2, tanh2(c));
    if (DOACC) acc = fma2(h2, wo, acc);
    return h2;
}

// SMEM layout (u64 units):
//  WL0  [8c][32k][8s] repacked Whh0   2048
//  WLX1 [8c][32k][8s] repacked Wih1   2048
//  WLH1 [8c][32k][8s] repacked Whh1   2048
//  B0   [64]  (b_ih0+b_hh0) pairs       64
//  WI0  [64]  W_ih0[:,0] pairs          64
//  B1   [64]  (b_ih1+b_hh1) pairs       64
//  WO   [7][16] fc1_w[t]*fc_w pairs    112
//  H0   [32k][320t]  (hA,hB) packed  10240
//  H1   [32k][320t]  (hA,hB) packed  10240
// total = 26928 u64 = 215424 B
#define SMEM_U64S 26928
#define SMEM_BYTES (SMEM_U64S * 8)

extern "C" __global__ void __launch_bounds__(NT, 1)
lstm_b262144_kernel(
    const float* __restrict__ x,
    const float* __restrict__ Wih0, const float* __restrict__ Whh0,
    const float* __restrict__ bih0, const float* __restrict__ bhh0,
    const float* __restrict__ Wih1, const float* __restrict__ Whh1,
    const float* __restrict__ bih1, const float* __restrict__ bhh1,
    const float* __restrict__ fcw,  const float* __restrict__ fcb,
    const float* __restrict__ fc1w, const float* __restrict__ fc1b,
    float* __restrict__ out, int B)
{
    extern __shared__ u64 sm[];
    u64* WL0  = sm;
    u64* WLX1 = WL0 + 2048;
    u64* WLH1 = WLX1 + 2048;
    u64* B0   = WLH1 + 2048;
    u64* WI0  = B0 + 64;
    u64* B1   = WI0 + 64;
    u64* WO   = B1 + 64;
    u64* H0   = WO + 112;
    u64* H1   = H0 + 32 * NT;

    const int tid = threadIdx.x;

    // ---- repack weights: WL[((c*32+k)*8)+s], s -> gate g=s>>1, sub=s&1,
    // rows r0 = g*32 + 4c + 2*sub, r0+1; col k. (validated mapping) ----
    for (int d = tid; d < 2048; d += NT) {
        int c = d >> 8, k = (d >> 3) & 31, s = d & 7;
        int g = s >> 1, sub = s & 1;
        int r0 = g * 32 + 4 * c + 2 * sub;
        WL0[d]  = pk2(Whh0[r0 * 32 + k], Whh0[(r0 + 1) * 32 + k]);
        WLX1[d] = pk2(Wih1[r0 * 32 + k], Wih1[(r0 + 1) * 32 + k]);
        WLH1[d] = pk2(Whh1[r0 * 32 + k], Whh1[(r0 + 1) * 32 + k]);
    }
    if (tid < 128) {
        ((float*)B0)[tid]  = bih0[tid] + bhh0[tid];
        ((float*)WI0)[tid] = Wih0[tid];
        ((float*)B1)[tid]  = bih1[tid] + bhh1[tid];
    }
    {
        float* WOf = (float*)WO;
        for (int d = tid; d < 224; d += NT) WOf[d] = fc1w[d >> 5] * fcw[d & 31];
    }
    __syncthreads();

    const long long Bll = B;
    const long long eA = (long long)blockIdx.x * EPC + tid;
    if (eA >= Bll) return;
    const long long eB = eA + NT;
    const bool storeB = (eB < Bll);
    const long long eBs = storeB ? eB : eA;  // clamp (duplicate compute)

    float xa[7], xb[7];
#pragma unroll
    for (int t = 0; t < 7; t++) { xa[t] = x[eA * 7 + t]; xb[t] = x[eBs * 7 + t]; }

    u64 hn[32];          // h-new staging: per-unit (hA,hB); reused by both layers
    u64 acca = 0ull, accb = 0ull;
    u64 dmy = 0ull;

    // ======================= t = 0 (peeled: h == 0, c == 0) =======================
    {
        u64 x2a = bc2(xa[0]), x2b = bc2(xb[0]);

        // --- layer 0: gates = x*wi + b only (h0 = 0, GEMV skipped exactly) ---
#pragma unroll
        for (int c = 0; c < 8; c++) {
            const int p0 = 2 * c;
            u64 wi0 = WI0[p0], wi1 = WI0[p0 + 1];
            u64 wg0 = WI0[p0 + 32], wg1 = WI0[p0 + 33];
            u64 wo0 = WI0[p0 + 48], wo1 = WI0[p0 + 49];
            u64 zai0 = fma2(x2a, wi0, B0[p0]),      zbi0 = fma2(x2b, wi0, B0[p0]);
            u64 zai1 = fma2(x2a, wi1, B0[p0 + 1]),  zbi1 = fma2(x2b, wi1, B0[p0 + 1]);
            u64 zag0 = fma2(x2a, wg0, B0[p0 + 32]), zbg0 = fma2(x2b, wg0, B0[p0 + 32]);
            u64 zag1 = fma2(x2a, wg1, B0[p0 + 33]), zbg1 = fma2(x2b, wg1, B0[p0 + 33]);
            u64 zao0 = fma2(x2a, wo0, B0[p0 + 48]), zbo0 = fma2(x2b, wo0, B0[p0 + 48]);
            u64 zao1 = fma2(x2a, wo1, B0[p0 + 49]), zbo1 = fma2(x2b, wo1, B0[p0 + 49]);

            u64 ca0, cb0, ca1, cb1;
            u64 h2a0 = lstm_upd0<false>(zai0, zag0, zao0, ca0, 0ull, dmy);
            u64 h2b0 = lstm_upd0<false>(zbi0, zbg0, zbo0, cb0, 0ull, dmy);
            u64 h2a1 = lstm_upd0<false>(zai1, zag1, zao1, ca1, 0ull, dmy);
            u64 h2b1 = lstm_upd0<false>(zbi1, zbg1, zbo1, cb1, 0ull, dmy);
            u64* r0 = g_cstate + (u64)p0 * BMAX;
            u64* r1 = g_cstate + (u64)(p0 + 1) * BMAX;
            r0[eA] = ca0; r0[eBs] = cb0;
            r1[eA] = ca1; r1[eBs] = cb1;

            float a0, a1, b0v, b1v;
            upk2(h2a0, a0, a1); upk2(h2b0, b0v, b1v);
            hn[4 * c + 0] = pk2(a0, b0v); hn[4 * c + 1] = pk2(a1, b1v);
            upk2(h2a1, a0, a1); upk2(h2b1, b0v, b1v);
            hn[4 * c + 2] = pk2(a0, b0v); hn[4 * c + 3] = pk2(a1, b1v);
        }
#pragma unroll
        for (int u = 0; u < 32; u++) H0[u * NT + tid] = hn[u];

        // --- layer 1: gates = b + Wih1 @ h0new (h1 = 0, h-GEMV skipped) ---
#pragma unroll
        for (int c = 0; c < 8; c++) {
            const int p0 = 2 * c;
            u64 zai0 = B1[p0],      zai1 = B1[p0 + 1];
            u64 zag0 = B1[p0 + 32], zag1 = B1[p0 + 33];
            u64 zao0 = B1[p0 + 48], zao1 = B1[p0 + 49];
            u64 zbi0 = zai0, zbi1 = zai1;
            u64 zbg0 = zag0, zbg1 = zag1;
            u64 zbo0 = zao0, zbo1 = zao1;

            const ulonglong2* wp = (const ulonglong2*)(WLX1 + (size_t)c * 256);
#pragma unroll 8
            for (int k = 0; k < 32; k++) {
                ulonglong2 q0 = wp[4 * k + 0];
                ulonglong2 q2 = wp[4 * k + 2];
                ulonglong2 q3 = wp[4 * k + 3];
                float ha, hb; upk2(H0[k * NT + tid], ha, hb);
                u64 hka = bc2(ha), hkb = bc2(hb);
                zai0 = fma2(hka, q0.x, zai0); zbi0 = fma2(hkb, q0.x, zbi0);
                zai1 = fma2(hka, q0.y, zai1); zbi1 = fma2(hkb, q0.y, zbi1);
                zag0 = fma2(hka, q2.x, zag0); zbg0 = fma2(hkb, q2.x, zbg0);
                zag1 = fma2(hka, q2.y, zag1); zbg1 = fma2(hkb, q2.y, zbg1);
                zao0 = fma2(hka, q3.x, zao0); zbo0 = fma2(hkb, q3.x, zbo0);
                zao1 = fma2(hka, q3.y, zao1); zbo1 = fma2(hkb, q3.y, zbo1);
            }
            u64 wo_p0 = WO[p0], wo_p1 = WO[p0 + 1];  // t = 0
            u64 ca0, cb0, ca1, cb1;
            u64 h2a0 = lstm_upd0<true>(zai0, zag0, zao0, ca0, wo_p0, acca);
            u64 h2b0 = lstm_upd0<true>(zbi0, zbg0, zbo0, cb0, wo_p0, accb);
            u64 h2a1 = lstm_upd0<true>(zai1, zag1, zao1, ca1, wo_p1, acca);
            u64 h2b1 = lstm_upd0<true>(zbi1, zbg1, zbo1, cb1, wo_p1, accb);
            u64* r0 = g_cstate + (u64)(16 + p0) * BMAX;
            u64* r1 = g_cstate + (u64)(16 + p0 + 1) * BMAX;
            r0[eA] = ca0; r0[eBs] = cb0;
            r1[eA] = ca1; r1[eBs] = cb1;

            float a0, a1, b0v, b1v;
            upk2(h2a0, a0, a1); upk2(h2b0, b0v, b1v);
            hn[4 * c + 0] = pk2(a0, b0v); hn[4 * c + 1] = pk2(a1, b1v);
            upk2(h2a1, a0, a1); upk2(h2b1, b0v, b1v);
            hn[4 * c + 2] = pk2(a0, b0v); hn[4 * c + 3] = pk2(a1, b1v);
        }
#pragma unroll
        for (int u = 0; u < 32; u++) H1[u * NT + tid] = hn[u];
    }

    // ======================= t = 1 .. 6 =======================
#pragma unroll 1
    for (int t = 1; t < 7; t++) {
        u64 x2a = bc2(xa[t]), x2b = bc2(xb[t]);

        // ========================= layer 0 =========================
#pragma unroll
        for (int c = 0; c < 8; c++) {
            const int p0 = 2 * c;
            u64* r0 = g_cstate + (u64)p0 * BMAX;
            u64* r1 = g_cstate + (u64)(p0 + 1) * BMAX;
            u64 ca0 = r0[eA], cb0 = r0[eBs];
            u64 ca1 = r1[eA], cb1 = r1[eBs];

            u64 wi0 = WI0[p0], wi1 = WI0[p0 + 1];
            u64 wf0 = WI0[p0 + 16], wf1 = WI0[p0 + 17];
            u64 wg0 = WI0[p0 + 32], wg1 = WI0[p0 + 33];
            u64 wo0 = WI0[p0 + 48], wo1 = WI0[p0 + 49];
            u64 zai0 = fma2(x2a, wi0, B0[p0]),      zbi0 = fma2(x2b, wi0, B0[p0]);
            u64 zai1 = fma2(x2a, wi1, B0[p0 + 1]),  zbi1 = fma2(x2b, wi1, B0[p0 + 1]);
            u64 zaf0 = fma2(x2a, wf0, B0[p0 + 16]), zbf0 = fma2(x2b, wf0, B0[p0 + 16]);
            u64 zaf1 = fma2(x2a, wf1, B0[p0 + 17]), zbf1 = fma2(x2b, wf1, B0[p0 + 17]);
            u64 zag0 = fma2(x2a, wg0, B0[p0 + 32]), zbg0 = fma2(x2b, wg0, B0[p0 + 32]);
            u64 zag1 = fma2(x2a, wg1, B0[p0 + 33]), zbg1 = fma2(x2b, wg1, B0[p0 + 33]);
            u64 zao0 = fma2(x2a, wo0, B0[p0 + 48]), zbo0 = fma2(x2b, wo0, B0[p0 + 48]);
            u64 zao1 = fma2(x2a, wo1, B0[p0 + 49]), zbo1 = fma2(x2b, wo1, B0[p0 + 49]);

            const ulonglong2* wp = (const ulonglong2*)(WL0 + (size_t)c * 256);
#pragma unroll 8
            for (int k = 0; k < 32; k++) {
                ulonglong2 q0 = wp[4 * k + 0];
                ulonglong2 q1 = wp[4 * k + 1];
                ulonglong2 q2 = wp[4 * k + 2];
                ulonglong2 q3 = wp[4 * k + 3];
                float ha, hb; upk2(H0[k * NT + tid], ha, hb);
                u64 hka = bc2(ha), hkb = bc2(hb);
                zai0 = fma2(hka, q0.x, zai0); zbi0 = fma2(hkb, q0.x, zbi0);
                zai1 = fma2(hka, q0.y, zai1); zbi1 = fma2(hkb, q0.y, zbi1);
                zaf0 = fma2(hka, q1.x, zaf0); zbf0 = fma2(hkb, q1.x, zbf0);
                zaf1 = fma2(hka, q1.y, zaf1); zbf1 = fma2(hkb, q1.y, zbf1);
                zag0 = fma2(hka, q2.x, zag0); zbg0 = fma2(hkb, q2.x, zbg0);
                zag1 = fma2(hka, q2.y, zag1); zbg1 = fma2(hkb, q2.y, zbg1);
                zao0 = fma2(hka, q3.x, zao0); zbo0 = fma2(hkb, q3.x, zbo0);
                zao1 = fma2(hka, q3.y, zao1); zbo1 = fma2(hkb, q3.y, zbo1);
            }
            u64 h2a0 = lstm_upd<false>(zai0, zaf0, zag0, zao0, ca0, 0ull, dmy);
            u64 h2b0 = lstm_upd<false>(zbi0, zbf0, zbg0, zbo0, cb0, 0ull, dmy);
            u64 h2a1 = lstm_upd<false>(zai1, zaf1, zag1, zao1, ca1, 0ull, dmy);
            u64 h2b1 = lstm_upd<false>(zbi1, zbf1, zbg1, zbo1, cb1, 0ull, dmy);
            if (t < 6) {
                r0[eA] = ca0; r0[eBs] = cb0;
                r1[eA] = ca1; r1[eBs] = cb1;
            }
            float a0, a1, b0v, b1v;
            upk2(h2a0, a0, a1); upk2(h2b0, b0v, b1v);
            hn[4 * c + 0] = pk2(a0, b0v); hn[4 * c + 1] = pk2(a1, b1v);
            upk2(h2a1, a0, a1); upk2(h2b1, b0v, b1v);
            hn[4 * c + 2] = pk2(a0, b0v); hn[4 * c + 3] = pk2(a1, b1v);
        }
#pragma unroll
        for (int u = 0; u < 32; u++) H0[u * NT + tid] = hn[u];

        // ========================= layer 1 =========================
#pragma unroll
        for (int c = 0; c < 8; c++) {
            const int p0 = 2 * c;
            u64* r0 = g_cstate + (u64)(16 + p0) * BMAX;
            u64* r1 = g_cstate + (u64)(16 + p0 + 1) * BMAX;
            u64 ca0 = r0[eA], cb0 = r0[eBs];
            u64 ca1 = r1[eA], cb1 = r1[eBs];

            u64 zai0 = B1[p0],      zai1 = B1[p0 + 1];
            u64 zaf0 = B1[p0 + 16], zaf1 = B1[p0 + 17];
            u64 zag0 = B1[p0 + 32], zag1 = B1[p0 + 33];
            u64 zao0 = B1[p0 + 48], zao1 = B1[p0 + 49];
            u64 zbi0 = zai0, zbi1 = zai1;
            u64 zbf0 = zaf0, zbf1 = zaf1;
            u64 zbg0 = zag0, zbg1 = zag1;
            u64 zbo0 = zao0, zbo1 = zao1;

            {
                const ulonglong2* wp = (const ulonglong2*)(WLX1 + (size_t)c * 256);
#pragma unroll 8
                for (int k = 0; k < 32; k++) {
                    ulonglong2 q0 = wp[4 * k + 0];
                    ulonglong2 q1 = wp[4 * k + 1];
                    ulonglong2 q2 = wp[4 * k + 2];
                    ulonglong2 q3 = wp[4 * k + 3];
                    float ha, hb; upk2(H0[k * NT + tid], ha, hb);
                    u64 hka = bc2(ha), hkb = bc2(hb);
                    zai0 = fma2(hka, q0.x, zai0); zbi0 = fma2(hkb, q0.x, zbi0);
                    zai1 = fma2(hka, q0.y, zai1); zbi1 = fma2(hkb, q0.y, zbi1);
                    zaf0 = fma2(hka, q1.x, zaf0); zbf0 = fma2(hkb, q1.x, zbf0);
                    zaf1 = fma2(hka, q1.y, zaf1); zbf1 = fma2(hkb, q1.y, zbf1);
                    zag0 = fma2(hka, q2.x, zag0); zbg0 = fma2(hkb, q2.x, zbg0);
                    zag1 = fma2(hka, q2.y, zag1); zbg1 = fma2(hkb, q2.y, zbg1);
                    zao0 = fma2(hka, q3.x, zao0); zbo0 = fma2(hkb, q3.x, zbo0);
                    zao1 = fma2(hka, q3.y, zao1); zbo1 = fma2(hkb, q3.y, zbo1);
                }
            }
            {
                const ulonglong2* wp = (const ulonglong2*)(WLH1 + (size_t)c * 256);
#pragma unroll 8
                for (int k = 0; k < 32; k++) {
                    ulonglong2 q0 = wp[4 * k + 0];
                    ulonglong2 q1 = wp[4 * k + 1];
                    ulonglong2 q2 = wp[4 * k + 2];
                    ulonglong2 q3 = wp[4 * k + 3];
                    float ha, hb; upk2(H1[k * NT + tid], ha, hb);
                    u64 hka = bc2(ha), hkb = bc2(hb);
                    zai0 = fma2(hka, q0.x, zai0); zbi0 = fma2(hkb, q0.x, zbi0);
                    zai1 = fma2(hka, q0.y, zai1); zbi1 = fma2(hkb, q0.y, zbi1);
                    zaf0 = fma2(hka, q1.x, zaf0); zbf0 = fma2(hkb, q1.x, zbf0);
                    zaf1 = fma2(hka, q1.y, zaf1); zbf1 = fma2(hkb, q1.y, zbf1);
                    zag0 = fma2(hka, q2.x, zag0); zbg0 = fma2(hkb, q2.x, zbg0);
                    zag1 = fma2(hka, q2.y, zag1); zbg1 = fma2(hkb, q2.y, zbg1);
                    zao0 = fma2(hka, q3.x, zao0); zbo0 = fma2(hkb, q3.x, zbo0);
                    zao1 = fma2(hka, q3.y, zao1); zbo1 = fma2(hkb, q3.y, zbo1);
                }
            }
            u64 wo_p0 = WO[t * 16 + p0], wo_p1 = WO[t * 16 + p0 + 1];
            u64 h2a0 = lstm_upd<true>(zai0, zaf0, zag0, zao0, ca0, wo_p0, acca);
            u64 h2b0 = lstm_upd<true>(zbi0, zbf0, zbg0, zbo0, cb0, wo_p0, accb);
            u64 h2a1 = lstm_upd<true>(zai1, zaf1, zag1, zao1, ca1, wo_p1, acca);
            u64 h2b1 = lstm_upd<true>(zbi1, zbf1, zbg1, zbo1, cb1, wo_p1, accb);
            if (t < 6) {
                r0[eA] = ca0; r0[eBs] = cb0;
                r1[eA] = ca1; r1[eBs] = cb1;
            }
            float a0, a1, b0v, b1v;
            upk2(h2a0, a0, a1); upk2(h2b0, b0v, b1v);
            hn[4 * c + 0] = pk2(a0, b0v); hn[4 * c + 1] = pk2(a1, b1v);
            upk2(h2a1, a0, a1); upk2(h2b1, b0v, b1v);
            hn[4 * c + 2] = pk2(a0, b0v); hn[4 * c + 3] = pk2(a1, b1v);
        }
#pragma unroll
        for (int u = 0; u < 32; u++) H1[u * NT + tid] = hn[u];
    }

    // y = Σ(acc) + fc_b*Σ_t fc1_w[t] + fc1_b
    float s = 0.0f;
#pragma unroll
    for (int t = 0; t < 7; t++) s += fc1w[t];
    float bias = fcb[0] * s + fc1b[0];

    float alo, ahi; upk2(acca, alo, ahi);
    out[eA] = alo + ahi + bias;
    if (storeB) {
        float blo, bhi; upk2(accb, blo, bhi);
        out[eB] = blo + bhi + bias;
    }
}

extern "C" void kernel_launch(void* const* d_in, const int* in_sizes, int n_in,
                              void* d_out, int out_size) {
    const float* x    = (const float*)d_in[0];
    const float* Wih0 = (const float*)d_in[1];
    const float* Whh0 = (const float*)d_in[2];
    const float* bih0 = (const float*)d_in[3];
    const float* bhh0 = (const float*)d_in[4];
    const float* Wih1 = (const float*)d_in[5];
    const float* Whh1 = (const float*)d_in[6];
    const float* bih1 = (const float*)d_in[7];
    const float* bhh1 = (const float*)d_in[8];
    const float* fcw  = (const float*)d_in[9];
    const float* fcb  = (const float*)d_in[10];
    const float* fc1w = (const float*)d_in[11];
    const float* fc1b = (const float*)d_in[12];
    float* out = (float*)d_out;

    const int B = in_sizes[0] / 7;  // [B, T=7, F=1]

    cudaFuncSetAttribute(lstm_b262144_kernel,
                         cudaFuncAttributeMaxDynamicSharedMemorySize, SMEM_BYTES);

    int grid = (B + EPC - 1) / EPC;
    lstm_b262144_kernel<<<grid, NT, SMEM_BYTES>>>(
        x, Wih0, Whh0, bih0, bhh0, Wih1, Whh1, bih1, bhh1,
        fcw, fcb, fc1w, fc1b, out, B);
}

// round 13
// speedup vs baseline: 1.3241x; 1.3241x over previous
#include <cuda_runtime.h>
#include <cuda_bf16.h>
#include <cstdint>

// ============================================================================
// 2-layer LSTM (H=32, T=7, F=1) + fc(H,1) + fc1(T,1), B=262144.
// R13 = R10 (best: 1284us) + EXPLICIT DISTANCE-1 SOFTWARE PIPELINE in the
// GEMV k-loops: named rotating prefetch registers load iter k+1's 4 weight
// quads + h while iter k's 16 FFMA2 execute (~21 instr ~52cy distance at
// 2.5 warps/SMSP > 29cy LDS latency). k-unroll 4 keeps code ~55KB.
// E=2 elems/thread, NT=320 (10 warps/SM), broadcast LDS.128 weights +
// LDS.64 h per k-iter -> 16 FFMA2 (f32x2); c-state in gmem scratch,
// h in SMEM, h-new staged in regs.
// ============================================================================

typedef unsigned long long u64;

#define NT 320          // threads per CTA (10 warps)
#define EPC (2 * NT)    // batch elements per CTA
#define BMAX 524288ull  // scratch capacity (>= B)

__device__ u64 g_cstate[32ull * BMAX];

__device__ __forceinline__ u64 pk2(float lo, float hi) {
    u64 r; asm("mov.b64 %0,{%1,%2};" : "=l"(r) : "f"(lo), "f"(hi)); return r;
}
__device__ __forceinline__ u64 bc2(float v) { return pk2(v, v); }
__device__ __forceinline__ void upk2(u64 v, float& lo, float& hi) {
    asm("mov.b64 {%0,%1},%2;" : "=f"(lo), "=f"(hi) : "l"(v));
}
__device__ __forceinline__ u64 fma2(u64 a, u64 b, u64 c) {
    u64 d; asm("fma.rn.f32x2 %0,%1,%2,%3;" : "=l"(d) : "l"(a), "l"(b), "l"(c)); return d;
}
__device__ __forceinline__ u64 mul2(u64 a, u64 b) {
    u64 d; asm("mul.rn.f32x2 %0,%1,%2;" : "=l"(d) : "l"(a), "l"(b)); return d;
}
__device__ __forceinline__ float ex2f(float x) {
    float y; asm("ex2.approx.f32 %0,%1;" : "=f"(y) : "f"(x)); return y;
}
__device__ __forceinline__ float rcpf(float x) {
    float y; asm("rcp.approx.f32 %0,%1;" : "=f"(y) : "f"(x)); return y;
}
__device__ __forceinline__ float fsig(float x) {
    float e = ex2f(-1.4426950408889634f * x);
    return rcpf(1.0f + e);
}
__device__ __forceinline__ float ftanhx(float x) {
    float t = fminf(-2.8853900817779268f * x, 120.0f);
    float e = ex2f(t);
    float r = rcpf(1.0f + e);
    return fmaf(-e, r, r);
}
__device__ __forceinline__ u64 sig2(u64 z) {
    float a, b; upk2(z, a, b); return pk2(fsig(a), fsig(b));
}
__device__ __forceinline__ u64 tanh2(u64 z) {
    float a, b; upk2(z, a, b); return pk2(ftanhx(a), ftanhx(b));
}

template <bool DOACC>
__device__ __forceinline__ u64 lstm_upd(
    u64 zi, u64 zf, u64 zg, u64 zo, u64& c, u64 wo, u64& acc)
{
    u64 i2 = sig2(zi);
    u64 f2 = sig2(zf);
    u64 g2 = tanh2(zg);
    u64 o2 = sig2(zo);
    c = fma2(f2, c, mul2(i2, g2));
    u64 h2 = mul2(o2, tanh2(c));
    if (DOACC) acc = fma2(h2, wo, acc);
    return h2;
}

// GEMV over 32 k with explicit distance-1 prefetch: load (k+1)'s 4 weight
// quads + packed h while computing k's 16 FFMA2. Last iteration peeled.
#define GEMV_FMAS(Q0, Q1, Q2, Q3, HKA, HKB)                                   \
    zai0 = fma2(HKA, (Q0).x, zai0); zbi0 = fma2(HKB, (Q0).x, zbi0);           \
    zai1 = fma2(HKA, (Q0).y, zai1); zbi1 = fma2(HKB, (Q0).y, zbi1);           \
    zaf0 = fma2(HKA, (Q1).x, zaf0); zbf0 = fma2(HKB, (Q1).x, zbf0);           \
    zaf1 = fma2(HKA, (Q1).y, zaf1); zbf1 = fma2(HKB, (Q1).y, zbf1);           \
    zag0 = fma2(HKA, (Q2).x, zag0); zbg0 = fma2(HKB, (Q2).x, zbg0);           \
    zag1 = fma2(HKA, (Q2).y, zag1); zbg1 = fma2(HKB, (Q2).y, zbg1);           \
    zao0 = fma2(HKA, (Q3).x, zao0); zbo0 = fma2(HKB, (Q3).x, zbo0);           \
    zao1 = fma2(HKA, (Q3).y, zao1); zbo1 = fma2(HKB, (Q3).y, zbo1);

#define GEMV32_PIPE(WPBASE, HPBASE)                                           \
    {                                                                         \
        const ulonglong2* __restrict__ wp = (WPBASE);                         \
        const u64* __restrict__ hp = (HPBASE);                                \
        ulonglong2 n0 = wp[0], n1 = wp[1], n2 = wp[2], n3 = wp[3];            \
        u64 nh = hp[0];                                                       \
        _Pragma("unroll 4")                                                   \
        for (int k = 0; k < 31; k++) {                                        \
            ulonglong2 q0 = n0, q1 = n1, q2 = n2, q3 = n3;                    \
            u64 hc = nh;                                                      \
            n0 = wp[4 * k + 4]; n1 = wp[4 * k + 5];                           \
            n2 = wp[4 * k + 6]; n3 = wp[4 * k + 7];                           \
            nh = hp[(k + 1) * NT];                                            \
            float ha, hb; upk2(hc, ha, hb);                                   \
            u64 hka = bc2(ha), hkb = bc2(hb);                                 \
            GEMV_FMAS(q0, q1, q2, q3, hka, hkb)                               \
        }                                                                     \
        {                                                                     \
            float ha, hb; upk2(nh, ha, hb);                                   \
            u64 hka = bc2(ha), hkb = bc2(hb);                                 \
            GEMV_FMAS(n0, n1, n2, n3, hka, hkb)                               \
        }                                                                     \
    }

// SMEM layout (u64 units):
//  WL0  [8c][32k][8s] repacked Whh0   2048
//  WLX1 [8c][32k][8s] repacked Wih1   2048
//  WLH1 [8c][32k][8s] repacked Whh1   2048
//  B0   [64]  (b_ih0+b_hh0) pairs       64
//  WI0  [64]  W_ih0[:,0] pairs          64
//  B1   [64]  (b_ih1+b_hh1) pairs       64
//  WO   [7][16] fc1_w[t]*fc_w pairs    112
//  H0   [32k][320t]  (hA,hB) packed  10240
//  H1   [32k][320t]  (hA,hB) packed  10240
// total = 26928 u64 = 215424 B
#define SMEM_U64S 26928
#define SMEM_BYTES (SMEM_U64S * 8)

extern "C" __global__ void __launch_bounds__(NT, 1)
lstm_b262144_kernel(
    const float* __restrict__ x,
    const float* __restrict__ Wih0, const float* __restrict__ Whh0,
    const float* __restrict__ bih0, const float* __restrict__ bhh0,
    const float* __restrict__ Wih1, const float* __restrict__ Whh1,
    const float* __restrict__ bih1, const float* __restrict__ bhh1,
    const float* __restrict__ fcw,  const float* __restrict__ fcb,
    const float* __restrict__ fc1w, const float* __restrict__ fc1b,
    float* __restrict__ out, int B)
{
    extern __shared__ u64 sm[];
    u64* WL0  = sm;
    u64* WLX1 = WL0 + 2048;
    u64* WLH1 = WLX1 + 2048;
    u64* B0   = WLH1 + 2048;
    u64* WI0  = B0 + 64;
    u64* B1   = WI0 + 64;
    u64* WO   = B1 + 64;
    u64* H0   = WO + 112;
    u64* H1   = H0 + 32 * NT;

    const int tid = threadIdx.x;

    // ---- repack weights: WL[((c*32+k)*8)+s], s -> gate g=s>>1, sub=s&1,
    // rows r0 = g*32 + 4c + 2*sub, r0+1; col k. (validated mapping) ----
    for (int d = tid; d < 2048; d += NT) {
        int c = d >> 8, k = (d >> 3) & 31, s = d & 7;
        int g = s >> 1, sub = s & 1;
        int r0 = g * 32 + 4 * c + 2 * sub;
        WL0[d]  = pk2(Whh0[r0 * 32 + k], Whh0[(r0 + 1) * 32 + k]);
        WLX1[d] = pk2(Wih1[r0 * 32 + k], Wih1[(r0 + 1) * 32 + k]);
        WLH1[d] = pk2(Whh1[r0 * 32 + k], Whh1[(r0 + 1) * 32 + k]);
    }
    if (tid < 128) {
        ((float*)B0)[tid]  = bih0[tid] + bhh0[tid];
        ((float*)WI0)[tid] = Wih0[tid];
        ((float*)B1)[tid]  = bih1[tid] + bhh1[tid];
    }
    {
        float* WOf = (float*)WO;
        for (int d = tid; d < 224; d += NT) WOf[d] = fc1w[d >> 5] * fcw[d & 31];
    }
    // zero h-state (own slots only)
#pragma unroll
    for (int u = 0; u < 32; u++) {
        H0[u * NT + tid] = 0ull;
        H1[u * NT + tid] = 0ull;
    }
    __syncthreads();

    const long long Bll = B;
    const long long eA = (long long)blockIdx.x * EPC + tid;
    if (eA >= Bll) return;
    const long long eB = eA + NT;
    const bool storeB = (eB < Bll);
    const long long eBs = storeB ? eB : eA;  // clamp (duplicate compute)

    float xa[7], xb[7];
#pragma unroll
    for (int t = 0; t < 7; t++) { xa[t] = x[eA * 7 + t]; xb[t] = x[eBs * 7 + t]; }

    u64 hn[32];          // h-new staging: per-unit (hA,hB); reused by both layers
    u64 acca = 0ull, accb = 0ull;
    u64 dmy = 0ull;

#pragma unroll 1
    for (int t = 0; t < 7; t++) {
        u64 x2a = bc2(xa[t]), x2b = bc2(xb[t]);

        // ========================= layer 0 =========================
#pragma unroll
        for (int c = 0; c < 8; c++) {
            const int p0 = 2 * c;
            // prefetch c-state (zeros at t==0)
            u64 ca0 = 0ull, cb0 = 0ull, ca1 = 0ull, cb1 = 0ull;
            u64* r0 = g_cstate + (u64)p0 * BMAX;
            u64* r1 = g_cstate + (u64)(p0 + 1) * BMAX;
            if (t) {
                ca0 = r0[eA]; cb0 = r0[eBs];
                ca1 = r1[eA]; cb1 = r1[eBs];
            }

            u64 wi0 = WI0[p0], wi1 = WI0[p0 + 1];
            u64 wf0 = WI0[p0 + 16], wf1 = WI0[p0 + 17];
            u64 wg0 = WI0[p0 + 32], wg1 = WI0[p0 + 33];
            u64 wo0 = WI0[p0 + 48], wo1 = WI0[p0 + 49];
            u64 zai0 = fma2(x2a, wi0, B0[p0]),      zbi0 = fma2(x2b, wi0, B0[p0]);
            u64 zai1 = fma2(x2a, wi1, B0[p0 + 1]),  zbi1 = fma2(x2b, wi1, B0[p0 + 1]);
            u64 zaf0 = fma2(x2a, wf0, B0[p0 + 16]), zbf0 = fma2(x2b, wf0, B0[p0 + 16]);
            u64 zaf1 = fma2(x2a, wf1, B0[p0 + 17]), zbf1 = fma2(x2b, wf1, B0[p0 + 17]);
            u64 zag0 = fma2(x2a, wg0, B0[p0 + 32]), zbg0 = fma2(x2b, wg0, B0[p0 + 32]);
            u64 zag1 = fma2(x2a, wg1, B0[p0 + 33]), zbg1 = fma2(x2b, wg1, B0[p0 + 33]);
            u64 zao0 = fma2(x2a, wo0, B0[p0 + 48]), zbo0 = fma2(x2b, wo0, B0[p0 + 48]);
            u64 zao1 = fma2(x2a, wo1, B0[p0 + 49]), zbo1 = fma2(x2b, wo1, B0[p0 + 49]);

            GEMV32_PIPE((const ulonglong2*)(WL0 + (size_t)c * 256), H0 + tid)

            u64 h2a0 = lstm_upd<false>(zai0, zaf0, zag0, zao0, ca0, 0ull, dmy);
            u64 h2b0 = lstm_upd<false>(zbi0, zbf0, zbg0, zbo0, cb0, 0ull, dmy);
            u64 h2a1 = lstm_upd<false>(zai1, zaf1, zag1, zao1, ca1, 0ull, dmy);
            u64 h2b1 = lstm_upd<false>(zbi1, zbf1, zbg1, zbo1, cb1, 0ull, dmy);
            if (t < 6) {
                r0[eA] = ca0; r0[eBs] = cb0;
                r1[eA] = ca1; r1[eBs] = cb1;
            }
            float a0, a1, b0v, b1v;
            upk2(h2a0, a0, a1); upk2(h2b0, b0v, b1v);
            hn[4 * c + 0] = pk2(a0, b0v); hn[4 * c + 1] = pk2(a1, b1v);
            upk2(h2a1, a0, a1); upk2(h2b1, b0v, b1v);
            hn[4 * c + 2] = pk2(a0, b0v); hn[4 * c + 3] = pk2(a1, b1v);
        }
        // publish new h0 (all reads of old h0 done; own slots only)
#pragma unroll
        for (int u = 0; u < 32; u++) H0[u * NT + tid] = hn[u];

        // ========================= layer 1 =========================
#pragma unroll
        for (int c = 0; c < 8; c++) {
            const int p0 = 2 * c;
            u64 ca0 = 0ull, cb0 = 0ull, ca1 = 0ull, cb1 = 0ull;
            u64* r0 = g_cstate + (u64)(16 + p0) * BMAX;
            u64* r1 = g_cstate + (u64)(16 + p0 + 1) * BMAX;
            if (t) {
                ca0 = r0[eA]; cb0 = r0[eBs];
                ca1 = r1[eA]; cb1 = r1[eBs];
            }

            u64 zai0 = B1[p0],      zai1 = B1[p0 + 1];
            u64 zaf0 = B1[p0 + 16], zaf1 = B1[p0 + 17];
            u64 zag0 = B1[p0 + 32], zag1 = B1[p0 + 33];
            u64 zao0 = B1[p0 + 48], zao1 = B1[p0 + 49];
            u64 zbi0 = zai0, zbi1 = zai1;
            u64 zbf0 = zaf0, zbf1 = zaf1;
            u64 zbg0 = zag0, zbg1 = zag1;
            u64 zbo0 = zao0, zbo1 = zao1;

            GEMV32_PIPE((const ulonglong2*)(WLX1 + (size_t)c * 256), H0 + tid)
            GEMV32_PIPE((const ulonglong2*)(WLH1 + (size_t)c * 256), H1 + tid)

            u64 wo_p0 = WO[t * 16 + p0], wo_p1 = WO[t * 16 + p0 + 1];
            u64 h2a0 = lstm_upd<true>(zai0, zaf0, zag0, zao0, ca0, wo_p0, acca);
            u64 h2b0 = lstm_upd<true>(zbi0, zbf0, zbg0, zbo0, cb0, wo_p0, accb);
            u64 h2a1 = lstm_upd<true>(zai1, zaf1, zag1, zao1, ca1, wo_p1, acca);
            u64 h2b1 = lstm_upd<true>(zbi1, zbf1, zbg1, zbo1, cb1, wo_p1, accb);
            if (t < 6) {
                r0[eA] = ca0; r0[eBs] = cb0;
                r1[eA] = ca1; r1[eBs] = cb1;
            }
            float a0, a1, b0v, b1v;
            upk2(h2a0, a0, a1); upk2(h2b0, b0v, b1v);
            hn[4 * c + 0] = pk2(a0, b0v); hn[4 * c + 1] = pk2(a1, b1v);
            upk2(h2a1, a0, a1); upk2(h2b1, b0v, b1v);
            hn[4 * c + 2] = pk2(a0, b0v); hn[4 * c + 3] = pk2(a1, b1v);
        }
#pragma unroll
        for (int u = 0; u < 32; u++) H1[u * NT + tid] = hn[u];
    }

    // y = Σ(acc) + fc_b*Σ_t fc1_w[t] + fc1_b
    float s = 0.0f;
#pragma unroll
    for (int t = 0; t < 7; t++) s += fc1w[t];
    float bias = fcb[0] * s + fc1b[0];

    float alo, ahi; upk2(acca, alo, ahi);
    out[eA] = alo + ahi + bias;
    if (storeB) {
        float blo, bhi; upk2(accb, blo, bhi);
        out[eB] = blo + bhi + bias;
    }
}

extern "C" void kernel_launch(void* const* d_in, const int* in_sizes, int n_in,
                              void* d_out, int out_size) {
    const float* x    = (const float*)d_in[0];
    const float* Wih0 = (const float*)d_in[1];
    const float* Whh0 = (const float*)d_in[2];
    const float* bih0 = (const float*)d_in[3];
    const float* bhh0 = (const float*)d_in[4];
    const float* Wih1 = (const float*)d_in[5];
    const float* Whh1 = (const float*)d_in[6];
    const float* bih1 = (const float*)d_in[7];
    const float* bhh1 = (const float*)d_in[8];
    const float* fcw  = (const float*)d_in[9];
    const float* fcb  = (const float*)d_in[10];
    const float* fc1w = (const float*)d_in[11];
    const float* fc1b = (const float*)d_in[12];
    float* out = (float*)d_out;

    const int B = in_sizes[0] / 7;  // [B, T=7, F=1]

    cudaFuncSetAttribute(lstm_b262144_kernel,
                         cudaFuncAttributeMaxDynamicSharedMemorySize, SMEM_BYTES);

    int grid = (B + EPC - 1) / EPC;
    lstm_b262144_kernel<<<grid, NT, SMEM_BYTES>>>(
        x, Wih0, Whh0, bih0, bhh0, Wih1, Whh1, bih1, bhh1,
        fcw, fcb, fc1w, fc1b, out, B);
}

// round 14
// speedup vs baseline: 1.3709x; 1.0354x over previous
#include <cuda_runtime.h>
#include <cuda_bf16.h>
#include <cstdint>

// ============================================================================
// 2-layer LSTM (H=32, T=7, F=1) + fc(H,1) + fc1(T,1), B=262144.
// R14: E=4 elems/thread; h-state in GMEM, DOUBLE-BUFFERED (kills the hn
// register staging that blocked E=4); weights-only SMEM (51.6KB).
// Per k-iter: 4x LDS.128 broadcast weights + 1x LDG.128 h quad feed
// 32 FFMA2 (f32x2) -> FMA-bound (L1 floor 470us < FMA floor 633us).
// NT=224, grid=293 (~2x148 SMs -> 99% wave utilization), 7 warps/SM.
// c-state in gmem (if(t) guard). h buf0 zeroed via capturable memsets.
// ============================================================================

typedef unsigned long long u64;

#define NT 224           // threads per CTA (7 warps)
#define EPC (4 * NT)     // 896 batch elements per CTA
#define QMAX 66560ull    // quad-slot capacity (>= grid*NT)

// h state: [layer][buf][k][qid], uint4 = h of unit k for elems e0..e3
__device__ uint4 g_h[2ull * 2ull * 32ull * QMAX];
// c state: row r = (lay*16 + pair)*2 + elemhalf; ulonglong2 = (c_e0,c_e1) or (c_e2,c_e3)
__device__ ulonglong2 g_c[64ull * QMAX];

__device__ __forceinline__ u64 pk2(float lo, float hi) {
    u64 r; asm("mov.b64 %0,{%1,%2};" : "=l"(r) : "f"(lo), "f"(hi)); return r;
}
__device__ __forceinline__ u64 bc2(float v) { return pk2(v, v); }
__device__ __forceinline__ void upk2(u64 v, float& lo, float& hi) {
    asm("mov.b64 {%0,%1},%2;" : "=f"(lo), "=f"(hi) : "l"(v));
}
__device__ __forceinline__ u64 fma2(u64 a, u64 b, u64 c) {
    u64 d; asm("fma.rn.f32x2 %0,%1,%2,%3;" : "=l"(d) : "l"(a), "l"(b), "l"(c)); return d;
}
__device__ __forceinline__ u64 mul2(u64 a, u64 b) {
    u64 d; asm("mul.rn.f32x2 %0,%1,%2;" : "=l"(d) : "l"(a), "l"(b)); return d;
}
__device__ __forceinline__ float ex2f(float x) {
    float y; asm("ex2.approx.f32 %0,%1;" : "=f"(y) : "f"(x)); return y;
}
__device__ __forceinline__ float rcpf(float x) {
    float y; asm("rcp.approx.f32 %0,%1;" : "=f"(y) : "f"(x)); return y;
}
__device__ __forceinline__ float fsig(float x) {
    float e = ex2f(-1.4426950408889634f * x);
    return rcpf(1.0f + e);
}
__device__ __forceinline__ float ftanhx(float x) {
    float t = fminf(-2.8853900817779268f * x, 120.0f);
    float e = ex2f(t);
    float r = rcpf(1.0f + e);
    return fmaf(-e, r, r);
}
__device__ __forceinline__ u64 sig2(u64 z) {
    float a, b; upk2(z, a, b); return pk2(fsig(a), fsig(b));
}
__device__ __forceinline__ u64 tanh2(u64 z) {
    float a, b; upk2(z, a, b); return pk2(ftanhx(a), ftanhx(b));
}

template <bool DOACC>
__device__ __forceinline__ u64 lstm_upd(
    u64 zi, u64 zf, u64 zg, u64 zo, u64& c, u64 wo, u64& acc)
{
    u64 i2 = sig2(zi);
    u64 f2 = sig2(zf);
    u64 g2 = tanh2(zg);
    u64 o2 = sig2(zo);
    c = fma2(f2, c, mul2(i2, g2));
    u64 h2 = mul2(o2, tanh2(c));
    if (DOACC) acc = fma2(h2, wo, acc);
    return h2;
}

// 8 gate-sub FMAs for one element's broadcast h against the 4 weight quads.
#define FMAB(HK, P)                                                           \
    P##i0 = fma2(HK, q0.x, P##i0); P##i1 = fma2(HK, q0.y, P##i1);             \
    P##f0 = fma2(HK, q1.x, P##f0); P##f1 = fma2(HK, q1.y, P##f1);             \
    P##g0 = fma2(HK, q2.x, P##g0); P##g1 = fma2(HK, q2.y, P##g1);             \
    P##o0 = fma2(HK, q3.x, P##o0); P##o1 = fma2(HK, q3.y, P##o1);

// GEMV over 32 k: weights from SMEM (broadcast LDS.128), h quad from gmem.
#define GEMV4(WPTR, HPTR)                                                     \
    {                                                                         \
        const ulonglong2* __restrict__ wp_ = (WPTR);                          \
        const uint4* __restrict__ hp_ = (HPTR);                               \
        _Pragma("unroll 8")                                                   \
        for (int k = 0; k < 32; k++) {                                        \
            ulonglong2 q0 = wp_[4 * k + 0];                                   \
            ulonglong2 q1 = wp_[4 * k + 1];                                   \
            ulonglong2 q2 = wp_[4 * k + 2];                                   \
            ulonglong2 q3 = wp_[4 * k + 3];                                   \
            uint4 hq = hp_[(size_t)k * QMAX];                                 \
            u64 hka = bc2(__uint_as_float(hq.x));                             \
            u64 hkb = bc2(__uint_as_float(hq.y));                             \
            u64 hkc = bc2(__uint_as_float(hq.z));                             \
            u64 hkd = bc2(__uint_as_float(hq.w));                             \
            FMAB(hka, zA) FMAB(hkb, zB) FMAB(hkc, zC) FMAB(hkd, zD)           \
        }                                                                     \
    }

// SMEM (u64 units): WL0 2048, WLX1 2048, WLH1 2048, B0 64, WI0 64, B1 64, WO 112
#define SMEM_U64S 6448
#define SMEM_BYTES (SMEM_U64S * 8)

extern "C" __global__ void __launch_bounds__(NT, 1)
lstm_b262144_kernel(
    const float* __restrict__ x,
    const float* __restrict__ Wih0, const float* __restrict__ Whh0,
    const float* __restrict__ bih0, const float* __restrict__ bhh0,
    const float* __restrict__ Wih1, const float* __restrict__ Whh1,
    const float* __restrict__ bih1, const float* __restrict__ bhh1,
    const float* __restrict__ fcw,  const float* __restrict__ fcb,
    const float* __restrict__ fc1w, const float* __restrict__ fc1b,
    float* __restrict__ out, int B)
{
    extern __shared__ u64 sm[];
    u64* WL0  = sm;
    u64* WLX1 = WL0 + 2048;
    u64* WLH1 = WLX1 + 2048;
    u64* B0   = WLH1 + 2048;
    u64* WI0  = B0 + 64;
    u64* B1   = WI0 + 64;
    u64* WO   = B1 + 64;

    const int tid = threadIdx.x;

    // ---- repack weights: WL[((c*32+k)*8)+s], s -> gate g=s>>1, sub=s&1,
    // rows r0 = g*32 + 4c + 2*sub, r0+1; col k. (validated mapping) ----
    for (int d = tid; d < 2048; d += NT) {
        int c = d >> 8, k = (d >> 3) & 31, s = d & 7;
        int g = s >> 1, sub = s & 1;
        int r0 = g * 32 + 4 * c + 2 * sub;
        WL0[d]  = pk2(Whh0[r0 * 32 + k], Whh0[(r0 + 1) * 32 + k]);
        WLX1[d] = pk2(Wih1[r0 * 32 + k], Wih1[(r0 + 1) * 32 + k]);
        WLH1[d] = pk2(Whh1[r0 * 32 + k], Whh1[(r0 + 1) * 32 + k]);
    }
    if (tid < 128) {
        ((float*)B0)[tid]  = bih0[tid] + bhh0[tid];
        ((float*)WI0)[tid] = Wih0[tid];
        ((float*)B1)[tid]  = bih1[tid] + bhh1[tid];
    }
    {
        float* WOf = (float*)WO;
        for (int d = tid; d < 224; d += NT) WOf[d] = fc1w[d >> 5] * fcw[d & 31];
    }
    __syncthreads();

    const long long Bll = B;
    const long long e0 = (long long)blockIdx.x * EPC + tid;
    if (e0 >= Bll) return;
    const long long e1r = e0 + NT, e2r = e0 + 2 * NT, e3r = e0 + 3 * NT;
    const bool l1v = (e1r < Bll), l2v = (e2r < Bll), l3v = (e3r < Bll);
    const long long e1 = l1v ? e1r : e0;
    const long long e2 = l2v ? e2r : e0;
    const long long e3 = l3v ? e3r : e0;

    const size_t qid = (size_t)blockIdx.x * NT + tid;

    float xa[7], xb[7], xc[7], xd[7];
#pragma unroll
    for (int t = 0; t < 7; t++) {
        xa[t] = x[e0 * 7 + t]; xb[t] = x[e1 * 7 + t];
        xc[t] = x[e2 * 7 + t]; xd[t] = x[e3 * 7 + t];
    }

    u64 acca = 0ull, accb = 0ull, accc = 0ull, accd = 0ull;
    u64 dmy = 0ull;

#pragma unroll 1
    for (int t = 0; t < 7; t++) {
        const int rb = t & 1, wb = rb ^ 1;
        const uint4* h0rd = g_h + ((size_t)(0 * 2 + rb) * 32) * QMAX + qid;
        uint4*       h0wr = g_h + ((size_t)(0 * 2 + wb) * 32) * QMAX + qid;
        const uint4* h1rd = g_h + ((size_t)(1 * 2 + rb) * 32) * QMAX + qid;
        uint4*       h1wr = g_h + ((size_t)(1 * 2 + wb) * 32) * QMAX + qid;

        u64 x2a = bc2(xa[t]), x2b = bc2(xb[t]), x2c = bc2(xc[t]), x2d = bc2(xd[t]);

        // ========================= layer 0 =========================
#pragma unroll 1
        for (int ch = 0; ch < 8; ch++) {
            const int p0 = 2 * ch;
            ulonglong2* cr0 = g_c + (size_t)((0 * 16 + p0) * 2 + 0) * QMAX + qid;
            ulonglong2* cr1 = g_c + (size_t)((0 * 16 + p0) * 2 + 1) * QMAX + qid;
            ulonglong2* cr2 = g_c + (size_t)((0 * 16 + p0 + 1) * 2 + 0) * QMAX + qid;
            ulonglong2* cr3 = g_c + (size_t)((0 * 16 + p0 + 1) * 2 + 1) * QMAX + qid;
            ulonglong2 cp0e01 = {0, 0}, cp0e23 = {0, 0}, cp1e01 = {0, 0}, cp1e23 = {0, 0};
            if (t) { cp0e01 = *cr0; cp0e23 = *cr1; cp1e01 = *cr2; cp1e23 = *cr3; }

            // x-projection init
            u64 wi0 = WI0[p0], wi1 = WI0[p0 + 1];
            u64 wf0 = WI0[p0 + 16], wf1 = WI0[p0 + 17];
            u64 wg0 = WI0[p0 + 32], wg1 = WI0[p0 + 33];
            u64 wo0 = WI0[p0 + 48], wo1 = WI0[p0 + 49];
            u64 bi0 = B0[p0], bi1 = B0[p0 + 1];
            u64 bf0 = B0[p0 + 16], bf1 = B0[p0 + 17];
            u64 bg0 = B0[p0 + 32], bg1 = B0[p0 + 33];
            u64 bo0 = B0[p0 + 48], bo1 = B0[p0 + 49];

            u64 zAi0 = fma2(x2a, wi0, bi0), zBi0 = fma2(x2b, wi0, bi0);
            u64 zCi0 = fma2(x2c, wi0, bi0), zDi0 = fma2(x2d, wi0, bi0);
            u64 zAi1 = fma2(x2a, wi1, bi1), zBi1 = fma2(x2b, wi1, bi1);
            u64 zCi1 = fma2(x2c, wi1, bi1), zDi1 = fma2(x2d, wi1, bi1);
            u64 zAf0 = fma2(x2a, wf0, bf0), zBf0 = fma2(x2b, wf0, bf0);
            u64 zCf0 = fma2(x2c, wf0, bf0), zDf0 = fma2(x2d, wf0, bf0);
            u64 zAf1 = fma2(x2a, wf1, bf1), zBf1 = fma2(x2b, wf1, bf1);
            u64 zCf1 = fma2(x2c, wf1, bf1), zDf1 = fma2(x2d, wf1, bf1);
            u64 zAg0 = fma2(x2a, wg0, bg0), zBg0 = fma2(x2b, wg0, bg0);
            u64 zCg0 = fma2(x2c, wg0, bg0), zDg0 = fma2(x2d, wg0, bg0);
            u64 zAg1 = fma2(x2a, wg1, bg1), zBg1 = fma2(x2b, wg1, bg1);
            u64 zCg1 = fma2(x2c, wg1, bg1), zDg1 = fma2(x2d, wg1, bg1);
            u64 zAo0 = fma2(x2a, wo0, bo0), zBo0 = fma2(x2b, wo0, bo0);
            u64 zCo0 = fma2(x2c, wo0, bo0), zDo0 = fma2(x2d, wo0, bo0);
            u64 zAo1 = fma2(x2a, wo1, bo1), zBo1 = fma2(x2b, wo1, bo1);
            u64 zCo1 = fma2(x2c, wo1, bo1), zDo1 = fma2(x2d, wo1, bo1);

            GEMV4((const ulonglong2*)(WL0 + (size_t)ch * 256), h0rd)

            u64 ca0 = cp0e01.x, cb0 = cp0e01.y, cc0 = cp0e23.x, cd0 = cp0e23.y;
            u64 ca1 = cp1e01.x, cb1 = cp1e01.y, cc1 = cp1e23.x, cd1 = cp1e23.y;
            u64 h2a0 = lstm_upd<false>(zAi0, zAf0, zAg0, zAo0, ca0, 0ull, dmy);
            u64 h2b0 = lstm_upd<false>(zBi0, zBf0, zBg0, zBo0, cb0, 0ull, dmy);
            u64 h2c0 = lstm_upd<false>(zCi0, zCf0, zCg0, zCo0, cc0, 0ull, dmy);
            u64 h2d0 = lstm_upd<false>(zDi0, zDf0, zDg0, zDo0, cd0, 0ull, dmy);
            u64 h2a1 = lstm_upd<false>(zAi1, zAf1, zAg1, zAo1, ca1, 0ull, dmy);
            u64 h2b1 = lstm_upd<false>(zBi1, zBf1, zBg1, zBo1, cb1, 0ull, dmy);
            u64 h2c1 = lstm_upd<false>(zCi1, zCf1, zCg1, zCo1, cc1, 0ull, dmy);
            u64 h2d1 = lstm_upd<false>(zDi1, zDf1, zDg1, zDo1, cd1, 0ull, dmy);
            if (t < 6) {
                *cr0 = make_ulonglong2(ca0, cb0);
                *cr1 = make_ulonglong2(cc0, cd0);
                *cr2 = make_ulonglong2(ca1, cb1);
                *cr3 = make_ulonglong2(cc1, cd1);
            }
            // repack h-new per UNIT across 4 elems and store
            float a0, a1, b0v, b1v, c0v, c1v, d0v, d1v;
            upk2(h2a0, a0, a1); upk2(h2b0, b0v, b1v); upk2(h2c0, c0v, c1v); upk2(h2d0, d0v, d1v);
            h0wr[(size_t)(4 * ch + 0) * QMAX] = make_uint4(
                __float_as_uint(a0), __float_as_uint(b0v), __float_as_uint(c0v), __float_as_uint(d0v));
            h0wr[(size_t)(4 * ch + 1) * QMAX] = make_uint4(
                __float_as_uint(a1), __float_as_uint(b1v), __float_as_uint(c1v), __float_as_uint(d1v));
            upk2(h2a1, a0, a1); upk2(h2b1, b0v, b1v); upk2(h2c1, c0v, c1v); upk2(h2d1, d0v, d1v);
            h0wr[(size_t)(4 * ch + 2) * QMAX] = make_uint4(
                __float_as_uint(a0), __float_as_uint(b0v), __float_as_uint(c0v), __float_as_uint(d0v));
            h0wr[(size_t)(4 * ch + 3) * QMAX] = make_uint4(
                __float_as_uint(a1), __float_as_uint(b1v), __float_as_uint(c1v), __float_as_uint(d1v));
        }

        // ========================= layer 1 =========================
#pragma unroll 1
        for (int ch = 0; ch < 8; ch++) {
            const int p0 = 2 * ch;
            ulonglong2* cr0 = g_c + (size_t)((1 * 16 + p0) * 2 + 0) * QMAX + qid;
            ulonglong2* cr1 = g_c + (size_t)((1 * 16 + p0) * 2 + 1) * QMAX + qid;
            ulonglong2* cr2 = g_c + (size_t)((1 * 16 + p0 + 1) * 2 + 0) * QMAX + qid;
            ulonglong2* cr3 = g_c + (size_t)((1 * 16 + p0 + 1) * 2 + 1) * QMAX + qid;
            ulonglong2 cp0e01 = {0, 0}, cp0e23 = {0, 0}, cp1e01 = {0, 0}, cp1e23 = {0, 0};
            if (t) { cp0e01 = *cr0; cp0e23 = *cr1; cp1e01 = *cr2; cp1e23 = *cr3; }

            u64 bi0 = B1[p0], bi1 = B1[p0 + 1];
            u64 bf0 = B1[p0 + 16], bf1 = B1[p0 + 17];
            u64 bg0 = B1[p0 + 32], bg1 = B1[p0 + 33];
            u64 bo0 = B1[p0 + 48], bo1 = B1[p0 + 49];
            u64 zAi0 = bi0, zBi0 = bi0, zCi0 = bi0, zDi0 = bi0;
            u64 zAi1 = bi1, zBi1 = bi1, zCi1 = bi1, zDi1 = bi1;
            u64 zAf0 = bf0, zBf0 = bf0, zCf0 = bf0, zDf0 = bf0;
            u64 zAf1 = bf1, zBf1 = bf1, zCf1 = bf1, zDf1 = bf1;
            u64 zAg0 = bg0, zBg0 = bg0, zCg0 = bg0, zDg0 = bg0;
            u64 zAg1 = bg1, zBg1 = bg1, zCg1 = bg1, zDg1 = bg1;
            u64 zAo0 = bo0, zBo0 = bo0, zCo0 = bo0, zDo0 = bo0;
            u64 zAo1 = bo1, zBo1 = bo1, zCo1 = bo1, zDo1 = bo1;

            GEMV4((const ulonglong2*)(WLX1 + (size_t)ch * 256), h0wr)  // h0 new
            GEMV4((const ulonglong2*)(WLH1 + (size_t)ch * 256), h1rd)  // h1 old

            u64 wo_p0 = WO[t * 16 + p0], wo_p1 = WO[t * 16 + p0 + 1];
            u64 ca0 = cp0e01.x, cb0 = cp0e01.y, cc0 = cp0e23.x, cd0 = cp0e23.y;
            u64 ca1 = cp1e01.x, cb1 = cp1e01.y, cc1 = cp1e23.x, cd1 = cp1e23.y;
            u64 h2a0 = lstm_upd<true>(zAi0, zAf0, zAg0, zAo0, ca0, wo_p0, acca);
            u64 h2b0 = lstm_upd<true>(zBi0, zBf0, zBg0, zBo0, cb0, wo_p0, accb);
            u64 h2c0 = lstm_upd<true>(zCi0, zCf0, zCg0, zCo0, cc0, wo_p0, accc);
            u64 h2d0 = lstm_upd<true>(zDi0, zDf0, zDg0, zDo0, cd0, wo_p0, accd);
            u64 h2a1 = lstm_upd<true>(zAi1, zAf1, zAg1, zAo1, ca1, wo_p1, acca);
            u64 h2b1 = lstm_upd<true>(zBi1, zBf1, zBg1, zBo1, cb1, wo_p1, accb);
            u64 h2c1 = lstm_upd<true>(zCi1, zCf1, zCg1, zCo1, cc1, wo_p1, accc);
            u64 h2d1 = lstm_upd<true>(zDi1, zDf1, zDg1, zDo1, cd1, wo_p1, accd);
            if (t < 6) {
                *cr0 = make_ulonglong2(ca0, cb0);
                *cr1 = make_ulonglong2(cc0, cd0);
                *cr2 = make_ulonglong2(ca1, cb1);
                *cr3 = make_ulonglong2(cc1, cd1);
            }
            if (t < 6) {
                float a0, a1, b0v, b1v, c0v, c1v, d0v, d1v;
                upk2(h2a0, a0, a1); upk2(h2b0, b0v, b1v); upk2(h2c0, c0v, c1v); upk2(h2d0, d0v, d1v);
                h1wr[(size_t)(4 * ch + 0) * QMAX] = make_uint4(
                    __float_as_uint(a0), __float_as_uint(b0v), __float_as_uint(c0v), __float_as_uint(d0v));
                h1wr[(size_t)(4 * ch + 1) * QMAX] = make_uint4(
                    __float_as_uint(a1), __float_as_uint(b1v), __float_as_uint(c1v), __float_as_uint(d1v));
                upk2(h2a1, a0, a1); upk2(h2b1, b0v, b1v); upk2(h2c1, c0v, c1v); upk2(h2d1, d0v, d1v);
                h1wr[(size_t)(4 * ch + 2) * QMAX] = make_uint4(
                    __float_as_uint(a0), __float_as_uint(b0v), __float_as_uint(c0v), __float_as_uint(d0v));
                h1wr[(size_t)(4 * ch + 3) * QMAX] = make_uint4(
                    __float_as_uint(a1), __float_as_uint(b1v), __float_as_uint(c1v), __float_as_uint(d1v));
            }
        }
    }

    // y = Σ(acc) + fc_b*Σ_t fc1_w[t] + fc1_b
    float s = 0.0f;
#pragma unroll
    for (int t = 0; t < 7; t++) s += fc1w[t];
    float bias = fcb[0] * s + fc1b[0];

    float lo, hi;
    upk2(acca, lo, hi); out[e0] = lo + hi + bias;
    if (l1v) { upk2(accb, lo, hi); out[e1r] = lo + hi + bias; }
    if (l2v) { upk2(accc, lo, hi); out[e2r] = lo + hi + bias; }
    if (l3v) { upk2(accd, lo, hi); out[e3r] = lo + hi + bias; }
}

extern "C" void kernel_launch(void* const* d_in, const int* in_sizes, int n_in,
                              void* d_out, int out_size) {
    const float* x    = (const float*)d_in[0];
    const float* Wih0 = (const float*)d_in[1];
    const float* Whh0 = (const float*)d_in[2];
    const float* bih0 = (const float*)d_in[3];
    const float* bhh0 = (const float*)d_in[4];
    const float* Wih1 = (const float*)d_in[5];
    const float* Whh1 = (const float*)d_in[6];
    const float* bih1 = (const float*)d_in[7];
    const float* bhh1 = (const float*)d_in[8];
    const float* fcw  = (const float*)d_in[9];
    const float* fcb  = (const float*)d_in[10];
    const float* fc1w = (const float*)d_in[11];
    const float* fc1b = (const float*)d_in[12];
    float* out = (float*)d_out;

    const int B = in_sizes[0] / 7;  // [B, T=7, F=1]

    cudaFuncSetAttribute(lstm_b262144_kernel,
                         cudaFuncAttributeMaxDynamicSharedMemorySize, SMEM_BYTES);

    // zero h read-buffer 0 of both layers (t=0 reads exact zeros);
    // cudaMemsetAsync is graph-capturable and replayed each launch.
    void* hbase = nullptr;
    cudaGetSymbolAddress(&hbase, g_h);
    const size_t slice = 32ull * QMAX * sizeof(uint4);   // one [buf] slice
    cudaMemsetAsync(hbase, 0, slice);                                  // lay0 buf0
    cudaMemsetAsync((char*)hbase + 2ull * slice, 0, slice);            // lay1 buf0

    int grid = (B + EPC - 1) / EPC;
    lstm_b262144_kernel<<<grid, NT, SMEM_BYTES>>>(
        x, Wih0, Whh0, bih0, bhh0, Wih1, Whh1, bih1, bhh1,
        fcw, fcb, fc1w, fc1b, out, B);
}